// round 11
// baseline (speedup 1.0000x reference)
#include <cuda_runtime.h>
#include <cuda_bf16.h>
#include <cstdint>
#include <math.h>

#define NIMG 8
#define CS   128
#define CT   256
#define PIX  4096           // 64*64
#define DTOT (CT*PIX)       // per image

// ---- scratch (__device__ globals; no allocation allowed) ----
__device__ float g_t[(size_t)NIMG*CT*PIX];
__device__ double g_acc[72];

// conv1 output: COMPACT odd-parity pixels only, [img][kc(8)][pix2048][32ch]
__device__ __align__(16) __nv_bfloat16 g_mHi[(size_t)NIMG*8*2048*32];
__device__ __align__(16) __nv_bfloat16 g_mLo[(size_t)NIMG*8*2048*32];
// gen1 output, int8 limbs: [img][kc2(4)][pix4096][64ch], x ~= 2^-12*(X1*128+X0)
__device__ __align__(16) char g_X1q[(size_t)NIMG*4*4096*64];
__device__ __align__(16) char g_X0q[(size_t)NIMG*4*4096*64];

// conv1 weights (row-major hi/lo)
__device__ __align__(16) __nv_bfloat16 g_WaHi[256*128], g_WaLo[256*128];
// conv2 weights bf16 packed (chunk = tap*4 + kc2; r = hilo*2048 + khalf*256 + co)
__device__ __align__(16) __nv_bfloat16 g_W1p[36*32768];
// conv3 weights int8 limbs packed: chunk = tap*4+kc2; within 32768 bytes:
// off = ((limb*2 + s)*256 + co)*32 + b ; w ~= 2^-17*(W1*128+W0); limb0 = W1
__device__ __align__(16) char g_W2q[36*32768];

// =====================================================================
// helpers (sm_80+ baseline PTX)
// =====================================================================
__device__ __forceinline__ uint32_t smem_u32(const void* p) {
    uint32_t a;
    asm("{ .reg .u64 t; cvta.to.shared.u64 t, %1; cvt.u32.u64 %0, t; }" : "=r"(a) : "l"(p));
    return a;
}
__device__ __forceinline__ void ldsm4(uint32_t* r, uint32_t addr) {
    asm volatile("ldmatrix.sync.aligned.m8n8.x4.shared.b16 {%0,%1,%2,%3}, [%4];"
                 : "=r"(r[0]), "=r"(r[1]), "=r"(r[2]), "=r"(r[3]) : "r"(addr));
}
__device__ __forceinline__ void mma16816(float* c, const uint32_t* a, uint32_t b0, uint32_t b1) {
    asm volatile("mma.sync.aligned.m16n8k16.row.col.f32.bf16.bf16.f32 "
                 "{%0,%1,%2,%3}, {%4,%5,%6,%7}, {%8,%9}, {%0,%1,%2,%3};"
                 : "+f"(c[0]), "+f"(c[1]), "+f"(c[2]), "+f"(c[3])
                 : "r"(a[0]), "r"(a[1]), "r"(a[2]), "r"(a[3]), "r"(b0), "r"(b1));
}
__device__ __forceinline__ void imma16832(int* c, const uint32_t* a, uint32_t b0, uint32_t b1) {
    asm volatile("mma.sync.aligned.m16n8k32.row.col.s32.s8.s8.s32 "
                 "{%0,%1,%2,%3}, {%4,%5,%6,%7}, {%8,%9}, {%0,%1,%2,%3};"
                 : "+r"(c[0]), "+r"(c[1]), "+r"(c[2]), "+r"(c[3])
                 : "r"(a[0]), "r"(a[1]), "r"(a[2]), "r"(a[3]), "r"(b0), "r"(b1));
}
__device__ __forceinline__ void cp16(uint32_t dst, const void* src, uint32_t sz) {
    asm volatile("cp.async.cg.shared.global [%0], [%1], 16, %2;"
                 :: "r"(dst), "l"(src), "r"(sz) : "memory");
}
__device__ __forceinline__ void cp_commit() {
    asm volatile("cp.async.commit_group;" ::: "memory");
}
__device__ __forceinline__ void cp_wait1() {
    asm volatile("cp.async.wait_group 1;" ::: "memory");
}
__device__ __forceinline__ void bf16split(float v, __nv_bfloat16& h, __nv_bfloat16& l) {
    h = __float2bfloat16(v);
    l = __float2bfloat16(v - __bfloat162float(h));
}

// =====================================================================
// Weight prep
// =====================================================================
__global__ void wprep_kernel(const float* __restrict__ Wa, const float* __restrict__ W1,
                             const float* __restrict__ W2) {
    int t = blockIdx.x * blockDim.x + threadIdx.x;
    if (t < 256*128) {
        float v = Wa[t];
        __nv_bfloat16 h, l;
        bf16split(v, h, l);
        g_WaHi[t] = h; g_WaLo[t] = l;
    }
    int u = t - 256*128;
    if (u >= 0 && u < 36*32768) {
        int chunk  = u >> 15;
        int within = u & 32767;
        int tap = chunk >> 2;
        int kc2 = chunk & 3;
        // W1 bf16 packing (r = hilo*2048 + khalf*256 + co, j in 16B row)
        {
            int r = within >> 3, j = within & 7;
            int hilo  = r >> 11;
            int khalf = (r >> 8) & 7;
            int co    = r & 255;
            int ci    = kc2 * 64 + khalf * 8 + j;
            int src   = co * 2304 + ci * 9 + tap;
            __nv_bfloat16 h, l;
            bf16split(W1[src], h, l);
            g_W1p[u] = hilo ? l : h;
        }
        // W2 int8 limb packing (off = ((limb*2+s)*256+co)*32 + b)
        {
            int limb = within >> 14;
            int s    = (within >> 13) & 1;
            int co   = (within >> 5) & 255;
            int b    = within & 31;
            int ci   = kc2 * 64 + s * 32 + b;
            int src  = co * 2304 + ci * 9 + tap;
            int q    = (int)rintf(W2[src] * 131072.f);   // sw = 2^-17
            int w1   = (q + 64) >> 7;
            int w0   = q - (w1 << 7);
            g_W2q[u] = (char)(limb == 0 ? w1 : w0);
        }
    }
}

__global__ void init_kernel() {
    if (threadIdx.x < 72) g_acc[threadIdx.x] = 0.0;
}

// =====================================================================
// conv1 (1x1, K=128): odd-parity pixels only (verified).
// =====================================================================
__global__ __launch_bounds__(256, 2)
void conv1_mma(const __nv_bfloat16* __restrict__ Whi, const __nv_bfloat16* __restrict__ Wlo,
               const float* __restrict__ bias, const float* __restrict__ in,
               __nv_bfloat16* __restrict__ outHi, __nv_bfloat16* __restrict__ outLo) {
    extern __shared__ char sm[];
    const int tid  = threadIdx.x;
    const int lane = tid & 31, wid = tid >> 5;
    const int m0   = blockIdx.y * 128;
    const int bx   = blockIdx.x;
    const int img  = bx >> 4;
    const int pix0 = (bx & 15) * 128;
    const float* inImg = in + (size_t)img * CS * PIX;

    constexpr int NCH = CS / 32;  // 4

    const int a_row = tid >> 1;
    const int a_k0  = (tid & 1) * 16;
    const int b_n   = tid & 127;
    const int b_sg  = tid >> 7;
    const int cpx  = pix0 + b_n;
    const int ch_h = cpx >> 5;
    const int ch_w = 2 * (cpx & 31) + ((ch_h + 1) & 1);
    const int bsrc = ch_h * 64 + ch_w;

    uint4 rAh[2], rAl[2];
    float rB[16];

    auto ldg_chunk = [&](int it) {
        const int c0 = it * 32;
        size_t aoff = (size_t)(m0 + a_row) * CS + c0 + a_k0;
        rAh[0] = *(const uint4*)(Whi + aoff);
        rAh[1] = *(const uint4*)(Whi + aoff + 8);
        rAl[0] = *(const uint4*)(Wlo + aoff);
        rAl[1] = *(const uint4*)(Wlo + aoff + 8);
        const float* p = inImg + (size_t)(c0 + b_sg * 16) * PIX + bsrc;
#pragma unroll
        for (int q = 0; q < 16; q++)
            rB[q] = __ldg(p + (size_t)q * PIX);
    };

    auto sts_chunk = [&](int s) {
        char* Ahi = sm + s * 32768;
        char* Alo = Ahi + 8192;
        char* Bhi = Ahi + 16384;
        char* Blo = Ahi + 24576;
        const int kh0 = a_k0 >> 3;
        *(uint4*)(Ahi + (kh0    ) * 2048 + a_row * 16) = rAh[0];
        *(uint4*)(Ahi + (kh0 + 1) * 2048 + a_row * 16) = rAh[1];
        *(uint4*)(Alo + (kh0    ) * 2048 + a_row * 16) = rAl[0];
        *(uint4*)(Alo + (kh0 + 1) * 2048 + a_row * 16) = rAl[1];
#pragma unroll
        for (int g = 0; g < 2; g++) {
            uint32_t hp[4], lp[4];
#pragma unroll
            for (int jp = 0; jp < 4; jp++) {
                float x0 = rB[g * 8 + 2 * jp], x1 = rB[g * 8 + 2 * jp + 1];
                __nv_bfloat16 hb0, lb0, hb1, lb1;
                bf16split(x0, hb0, lb0);
                bf16split(x1, hb1, lb1);
                hp[jp] = (uint32_t)__bfloat16_as_ushort(hb0)
                       | ((uint32_t)__bfloat16_as_ushort(hb1) << 16);
                lp[jp] = (uint32_t)__bfloat16_as_ushort(lb0)
                       | ((uint32_t)__bfloat16_as_ushort(lb1) << 16);
            }
            const int kh = b_sg * 2 + g;
            *(uint4*)(Bhi + kh * 2048 + b_n * 16) = make_uint4(hp[0], hp[1], hp[2], hp[3]);
            *(uint4*)(Blo + kh * 2048 + b_n * 16) = make_uint4(lp[0], lp[1], lp[2], lp[3]);
        }
    };

    float acc[4][4][4];
#pragma unroll
    for (int i = 0; i < 4; i++)
#pragma unroll
        for (int j = 0; j < 4; j++)
#pragma unroll
            for (int k = 0; k < 4; k++) acc[i][j][k] = 0.f;

    const int warp_m = wid & 1;
    const int warp_n = wid >> 1;
    const uint32_t smem0 = smem_u32(sm);
    const int lrow = (lane & 7) + ((lane >> 3) & 1) * 8;
    const int lkh  = (lane >> 4);

    ldg_chunk(0);
    sts_chunk(0);
    __syncthreads();

    for (int it = 0; it < NCH; ++it) {
        if (it + 1 < NCH) ldg_chunk(it + 1);
        const uint32_t S = smem0 + (it & 1) * 32768;
#pragma unroll
        for (int k16 = 0; k16 < 2; ++k16) {
            const uint32_t kbase = S + (k16 * 2 + lkh) * 2048;
            uint32_t bh[2][4], bl[2][4];
#pragma unroll
            for (int ng = 0; ng < 2; ++ng) {
                const uint32_t bd = kbase + 16384 + (warp_n * 32 + ng * 16 + lrow) * 16;
                ldsm4(bh[ng], bd);
                ldsm4(bl[ng], bd + 8192);
            }
#pragma unroll
            for (int mt = 0; mt < 4; ++mt) {
                uint32_t ah[4], al[4];
                const uint32_t ad = kbase + (warp_m * 64 + mt * 16 + lrow) * 16;
                ldsm4(ah, ad);
                ldsm4(al, ad + 8192);
#pragma unroll
                for (int nt = 0; nt < 4; ++nt)
                    mma16816(acc[mt][nt], ah, bh[nt >> 1][nt & 1], bh[nt >> 1][2 + (nt & 1)]);
#pragma unroll
                for (int nt = 0; nt < 4; ++nt)
                    mma16816(acc[mt][nt], ah, bl[nt >> 1][nt & 1], bl[nt >> 1][2 + (nt & 1)]);
#pragma unroll
                for (int nt = 0; nt < 4; ++nt)
                    mma16816(acc[mt][nt], al, bh[nt >> 1][nt & 1], bh[nt >> 1][2 + (nt & 1)]);
            }
        }
        if (it + 1 < NCH) sts_chunk((it + 1) & 1);
        __syncthreads();
    }

    const int l4 = lane >> 2, l2 = lane & 3;
    const size_t imgbase = (size_t)img * 8 * 2048 * 32;
#pragma unroll
    for (int mt = 0; mt < 4; ++mt) {
        const int co0 = m0 + warp_m * 64 + mt * 16 + l4;
        const float bi0 = bias[co0], bi1 = bias[co0 + 8];
#pragma unroll
        for (int nt = 0; nt < 4; ++nt) {
            const int p = pix0 + warp_n * 32 + nt * 8 + l2 * 2;
            float v0 = acc[mt][nt][0] + bi0;
            float v1 = acc[mt][nt][1] + bi0;
            float v2 = acc[mt][nt][2] + bi1;
            float v3 = acc[mt][nt][3] + bi1;
            const size_t o00 = imgbase + ((size_t)(co0 >> 5) * 2048 + p) * 32 + (co0 & 31);
            const size_t o10 = imgbase + ((size_t)((co0 + 8) >> 5) * 2048 + p) * 32 + ((co0 + 8) & 31);
            __nv_bfloat16 h, l;
            bf16split(v0, h, l); outHi[o00]      = h; outLo[o00]      = l;
            bf16split(v1, h, l); outHi[o00 + 32] = h; outLo[o00 + 32] = l;
            bf16split(v2, h, l); outHi[o10]      = h; outLo[o10]      = l;
            bf16split(v3, h, l); outHi[o10 + 32] = h; outLo[o10 + 32] = l;
        }
    }
}

// =====================================================================
// conv2 (gen1, polyphase, bf16x3; epilogue quantizes to int8 limbs)
// =====================================================================
#define STG 98304

#define K16_BODY(kbA, kbB)                                                          \
    {                                                                               \
        uint32_t bh[2][4], bl[2][4], ah[4][4];                                      \
        _Pragma("unroll")                                                           \
        for (int ng = 0; ng < 2; ++ng) {                                            \
            const uint32_t bd = (kbB) + (warp_n * 32 + ng * 16 + lrow) * 16;        \
            ldsm4(bh[ng], bd);                                                      \
            ldsm4(bl[ng], bd + 16384);                                              \
        }                                                                           \
        _Pragma("unroll")                                                           \
        for (int mt = 0; mt < 4; ++mt)                                              \
            ldsm4(ah[mt], (kbA) + (warp_m * 64 + mt * 16 + lrow) * 16);             \
        _Pragma("unroll")                                                           \
        for (int mt = 0; mt < 4; ++mt)                                              \
            _Pragma("unroll")                                                       \
            for (int nt = 0; nt < 4; ++nt)                                          \
                mma16816(acc[mt][nt], ah[mt],                                       \
                         bh[nt >> 1][nt & 1], bh[nt >> 1][2 + (nt & 1)]);           \
        _Pragma("unroll")                                                           \
        for (int mt = 0; mt < 4; ++mt)                                              \
            _Pragma("unroll")                                                       \
            for (int nt = 0; nt < 4; ++nt)                                          \
                mma16816(acc[mt][nt], ah[mt],                                       \
                         bl[nt >> 1][nt & 1], bl[nt >> 1][2 + (nt & 1)]);           \
        _Pragma("unroll")                                                           \
        for (int mt = 0; mt < 4; ++mt) {                                            \
            uint32_t al[4];                                                         \
            ldsm4(al, (kbA) + 32768 + (warp_m * 64 + mt * 16 + lrow) * 16);         \
            _Pragma("unroll")                                                       \
            for (int nt = 0; nt < 4; ++nt)                                          \
                mma16816(acc[mt][nt], al,                                           \
                         bh[nt >> 1][nt & 1], bh[nt >> 1][2 + (nt & 1)]);           \
        }                                                                           \
    }

__global__ __launch_bounds__(512, 1)
void conv2_poly(const __nv_bfloat16* __restrict__ Wp,
                const float* __restrict__ bias,
                const __nv_bfloat16* __restrict__ actHi,
                const __nv_bfloat16* __restrict__ actLo,
                char* __restrict__ X1p,
                char* __restrict__ X0p) {
    extern __shared__ char sm[];
    const int tid  = threadIdx.x;
    const int lane = tid & 31, wid = tid >> 5;
    const int bx   = blockIdx.x;
    const int img  = bx >> 5;
    const int rem  = bx & 31;
    const int P    = rem >> 4;
    const int h0   = (rem & 15) * 4;

    const int NT  = 4 + P;
    const int NCH = NT * 4;
    const uint32_t smem0 = smem_u32(sm);
    const uint32_t dstA0 = smem0 + tid * 16;
    const uint32_t dstB0 = smem0 + 65536 + tid * 16;

    const __nv_bfloat16* aPtr = Wp + tid * 8;
    uint32_t bOff[2];
    uint32_t bOk = 0;

    auto setup_tap = [&](int tap_t) {
        const int tapid = P ? (2 * tap_t) : (2 * tap_t + 1);
        const int dh = tapid / 3 - 1, dw = tapid % 3 - 1;
        aPtr = Wp + (size_t)tapid * 4 * 32768 + tid * 8;
        bOk = 0;
#pragma unroll
        for (int r = 0; r < 2; ++r) {
            const int br = tid + 512 * r;
            const int khalf = (br >> 7) & 7;
            const int px    = br & 127;
            const int row = h0 + (px >> 5);
            const int ow  = 2 * (px & 31) + ((P + row) & 1);
            const int h = row + dh, w = ow + dw;
            const bool ok = ((unsigned)h < 64u) & ((unsigned)w < 64u);
            const int ci = ok ? ((w - ((h + 1) & 1)) >> 1) : 0;
            const int hpix = ok ? (h * 32 + ci) : 0;
            bOff[r] = ((uint32_t)(img * 8 + (khalf >> 2)) * 2048 + hpix) * 32 + (khalf & 3) * 8;
            bOk |= (ok ? 1u : 0u) << r;
        }
    };

    auto issue = [&](int it) {
        const uint32_t sb = (uint32_t)(it & 1) * STG;
        const int kc2 = it & 3;
        if (kc2 == 0) setup_tap(it >> 2);
        const __nv_bfloat16* a = aPtr + kc2 * 32768;
#pragma unroll
        for (int i = 0; i < 8; i++)
            cp16(dstA0 + sb + 8192u * i, a + 4096 * i, 16u);
        const uint32_t kadd = (uint32_t)kc2 * 131072u;
        const uint32_t s0 = (bOk & 1u) ? 16u : 0u;
        const uint32_t s1 = (bOk & 2u) ? 16u : 0u;
        cp16(dstB0 + sb,         actHi + bOff[0] + kadd, s0);
        cp16(dstB0 + sb + 8192,  actHi + bOff[1] + kadd, s1);
        cp16(dstB0 + sb + 16384, actLo + bOff[0] + kadd, s0);
        cp16(dstB0 + sb + 24576, actLo + bOff[1] + kadd, s1);
    };

    float acc[4][4][4];
#pragma unroll
    for (int i = 0; i < 4; i++)
#pragma unroll
        for (int j = 0; j < 4; j++)
#pragma unroll
            for (int k = 0; k < 4; k++) acc[i][j][k] = 0.f;

    const int warp_m = wid >> 2;
    const int warp_n = wid & 3;
    const int lrow = (lane & 7) + ((lane >> 3) & 1) * 8;
    const int lkh  = (lane >> 4);

    issue(0); cp_commit();

    for (int it = 0; it < NCH; ++it) {
        if (it + 1 < NCH) issue(it + 1);
        cp_commit();
        cp_wait1();
        __syncthreads();

        const uint32_t S = smem0 + (it & 1) * STG;
#pragma unroll
        for (int k16 = 0; k16 < 4; ++k16) {
            const int khl = k16 * 2 + lkh;
            const uint32_t kbA = S + khl * 4096;
            const uint32_t kbB = S + 65536 + khl * 2048;
            K16_BODY(kbA, kbB)
        }
        __syncthreads();
    }

    // epilogue: bias + relu, quantize to int8 limbs (sx = 2^-12)
    const int l4 = lane >> 2, l2 = lane & 3;
    const int row = h0 + warp_n;
    const int wpar = (P + row) & 1;
#pragma unroll
    for (int mt = 0; mt < 4; ++mt) {
        const int co0 = warp_m * 64 + mt * 16 + l4;
        const float bi0 = bias[co0], bi1 = bias[co0 + 8];
        const size_t pb0 = ((size_t)(img * 4 + (co0 >> 6)) * 4096) * 64;
        const int c0c = co0 & 63;
#pragma unroll
        for (int nt = 0; nt < 4; ++nt) {
            const int j0 = nt * 8 + l2 * 2;
            const int pix0e = row * 64 + 2 * j0 + wpar;
            const int pix1e = pix0e + 2;
            float v0 = fmaxf(acc[mt][nt][0] + bi0, 0.f);
            float v1 = fmaxf(acc[mt][nt][1] + bi0, 0.f);
            float v2 = fmaxf(acc[mt][nt][2] + bi1, 0.f);
            float v3 = fmaxf(acc[mt][nt][3] + bi1, 0.f);
            int q0 = (int)rintf(v0 * 4096.f);
            int q1 = (int)rintf(v1 * 4096.f);
            int q2 = (int)rintf(v2 * 4096.f);
            int q3 = (int)rintf(v3 * 4096.f);
            int h0q = (q0 + 64) >> 7, h1q = (q1 + 64) >> 7;
            int h2q = (q2 + 64) >> 7, h3q = (q3 + 64) >> 7;
            const size_t a0 = pb0 + (size_t)pix0e * 64 + c0c;
            const size_t a1 = pb0 + (size_t)pix1e * 64 + c0c;
            X1p[a0]     = (char)h0q; X0p[a0]     = (char)(q0 - (h0q << 7));
            X1p[a1]     = (char)h1q; X0p[a1]     = (char)(q1 - (h1q << 7));
            X1p[a0 + 8] = (char)h2q; X0p[a0 + 8] = (char)(q2 - (h2q << 7));
            X1p[a1 + 8] = (char)h3q; X0p[a1 + 8] = (char)(q3 - (h3q << 7));
        }
    }
}

// =====================================================================
// conv3 (dense 3x3) via IMMA int8x2. grid 512 = img*64 + mb*32 + pxtile.
// 512 thr, CTA tile 128co x 128px, BK=64 (2 x k32), 2-stage 32KB stages.
// Stage: A [limb2][s2][co128][32B] @+0 (16KB), B same for px @+16384.
// =====================================================================
__global__ __launch_bounds__(512, 1)
void conv3_imma(const char* __restrict__ Wq,
                const float* __restrict__ bias,
                const char* __restrict__ X1p,
                const char* __restrict__ X0p,
                float* __restrict__ outF32) {
    extern __shared__ char sm[];
    const int tid  = threadIdx.x;
    const int lane = tid & 31, wid = tid >> 5;
    const int bx   = blockIdx.x;
    const int img  = bx >> 6;
    const int rem  = bx & 63;
    const int mb   = rem >> 5;
    const int pix0 = (rem & 31) * 128;
    const int h0   = pix0 >> 6;

    constexpr int NCH = 36;
    const uint32_t smem0 = smem_u32(sm);

    // producer constants
    const uint32_t aoff0 = ((uint32_t)(tid >> 8)) * 8192u + (uint32_t)mb * 4096u
                         + ((uint32_t)((tid >> 1) & 127)) * 32u + ((uint32_t)(tid & 1)) * 16u;
    const uint32_t dstA0 = smem0 + tid * 16;
    const int bs    = (tid >> 8) & 1;
    const int bpx   = (tid >> 1) & 127;
    const int bhalf = tid & 1;
    const uint32_t dstB0 = smem0 + 16384 + bs * 4096 + bpx * 32 + bhalf * 16;

    const char* aBase = Wq;
    uint32_t bSrc = 0, bOkSz = 0;

    auto setup_tap = [&](int tap) {
        const int dh = tap / 3 - 1, dw = tap % 3 - 1;
        aBase = Wq + (size_t)tap * 4 * 32768;
        const int h = h0 + (bpx >> 6) + dh, w = (bpx & 63) + dw;
        const bool ok = ((unsigned)h < 64u) & ((unsigned)w < 64u);
        const int sp = ok ? (h * 64 + w) : 0;
        bSrc = ((uint32_t)(img * 4) * 4096 + sp) * 64 + bs * 32 + bhalf * 16;
        bOkSz = ok ? 16u : 0u;
    };

    auto issue = [&](int it) {
        const uint32_t sb = (uint32_t)(it & 1) * 32768u;
        const int kc2 = it & 3;
        if (kc2 == 0) setup_tap(it >> 2);
        const char* a = aBase + kc2 * 32768;
        cp16(dstA0 + sb,        a + aoff0,          16u);
        cp16(dstA0 + sb + 8192, a + aoff0 + 16384,  16u);
        const uint32_t kadd = (uint32_t)kc2 * 262144u;
        cp16(dstB0 + sb,        X1p + bSrc + kadd, bOkSz);
        cp16(dstB0 + sb + 8192, X0p + bSrc + kadd, bOkSz);
    };

    int acc11[2][4][4], accmid[2][4][4];
#pragma unroll
    for (int i = 0; i < 2; i++)
#pragma unroll
        for (int j = 0; j < 4; j++)
#pragma unroll
            for (int k = 0; k < 4; k++) { acc11[i][j][k] = 0; accmid[i][j][k] = 0; }

    const int warp_m = wid >> 2;   // 0..3 -> 32 co each
    const int warp_n = wid & 3;    // 0..3 -> 32 px each
    const uint32_t laneA = (uint32_t)(((lane & 7) + ((lane >> 3) & 1) * 8)) * 32 + (lane >> 4) * 16;
    const uint32_t laneB = (uint32_t)(((lane & 7) + ((lane >> 4) & 1) * 8)) * 32 + ((lane >> 3) & 1) * 16;

    issue(0); cp_commit();

    for (int it = 0; it < NCH; ++it) {
        if (it + 1 < NCH) issue(it + 1);
        cp_commit();
        cp_wait1();
        __syncthreads();

        const uint32_t S = smem0 + (it & 1) * 32768;
#pragma unroll
        for (int s = 0; s < 2; ++s) {
            const uint32_t Ab = S + s * 4096 + (uint32_t)(warp_m * 32) * 32 + laneA;
            const uint32_t Bb = S + 16384 + s * 4096 + (uint32_t)(warp_n * 32) * 32 + laneB;
            uint32_t b0f[2][4], b1f[2][4], aw[2][4];
            ldsm4(b0f[0], Bb);                 // X1, px 0-15  (nt 0,1)
            ldsm4(b0f[1], Bb + 512);           // X1, px 16-31 (nt 2,3)
            ldsm4(b1f[0], Bb + 8192);          // X0
            ldsm4(b1f[1], Bb + 8192 + 512);
            ldsm4(aw[0], Ab);                  // W1, mt0
            ldsm4(aw[1], Ab + 512);            // W1, mt1
            // pass1: W1*X1 -> acc11
#pragma unroll
            for (int mt = 0; mt < 2; ++mt)
#pragma unroll
                for (int nt = 0; nt < 4; ++nt)
                    imma16832(acc11[mt][nt], aw[mt],
                              b0f[nt >> 1][2 * (nt & 1)], b0f[nt >> 1][2 * (nt & 1) + 1]);
            // pass2: W1*X0 -> accmid
#pragma unroll
            for (int mt = 0; mt < 2; ++mt)
#pragma unroll
                for (int nt = 0; nt < 4; ++nt)
                    imma16832(accmid[mt][nt], aw[mt],
                              b1f[nt >> 1][2 * (nt & 1)], b1f[nt >> 1][2 * (nt & 1) + 1]);
            // pass3: W0*X1 -> accmid
            ldsm4(aw[0], Ab + 8192);
            ldsm4(aw[1], Ab + 8192 + 512);
#pragma unroll
            for (int mt = 0; mt < 2; ++mt)
#pragma unroll
                for (int nt = 0; nt < 4; ++nt)
                    imma16832(accmid[mt][nt], aw[mt],
                              b0f[nt >> 1][2 * (nt & 1)], b0f[nt >> 1][2 * (nt & 1) + 1]);
        }
        __syncthreads();
    }

    // epilogue: v = acc11*2^-15 + accmid*2^-22 + bias
    const int l4 = lane >> 2, l2 = lane & 3;
    float* outImg = outF32 + (size_t)img * CT * PIX;
#pragma unroll
    for (int mt = 0; mt < 2; ++mt) {
        const int co0 = mb * 128 + warp_m * 32 + mt * 16 + l4;
        const float bi0 = bias[co0], bi1 = bias[co0 + 8];
#pragma unroll
        for (int nt = 0; nt < 4; ++nt) {
            const int p = pix0 + warp_n * 32 + nt * 8 + l2 * 2;
            float v0 = (float)acc11[mt][nt][0] * 0x1p-15f + (float)accmid[mt][nt][0] * 0x1p-22f + bi0;
            float v1 = (float)acc11[mt][nt][1] * 0x1p-15f + (float)accmid[mt][nt][1] * 0x1p-22f + bi0;
            float v2 = (float)acc11[mt][nt][2] * 0x1p-15f + (float)accmid[mt][nt][2] * 0x1p-22f + bi1;
            float v3 = (float)acc11[mt][nt][3] * 0x1p-15f + (float)accmid[mt][nt][3] * 0x1p-22f + bi1;
            *(float2*)(outImg + (size_t)co0 * PIX + p)       = make_float2(v0, v1);
            *(float2*)(outImg + (size_t)(co0 + 8) * PIX + p) = make_float2(v2, v3);
        }
    }
}

// =====================================================================
// pairwise dots + target norms (unchanged, verified)
// =====================================================================
__global__ __launch_bounds__(256)
void dot_kernel(const float* __restrict__ p, const float* __restrict__ t) {
    const int tid = threadIdx.x;
    const int d0  = blockIdx.x * 2048 + tid;

    float dacc[8][8];
    float tn[8];
#pragma unroll
    for (int i = 0; i < 8; i++) {
        tn[i] = 0.f;
#pragma unroll
        for (int j = 0; j < 8; j++) dacc[i][j] = 0.f;
    }
#pragma unroll 2
    for (int it = 0; it < 8; it++) {
        int d = d0 + it * 256;
        float pv[8], tv[8];
#pragma unroll
        for (int i = 0; i < 8; i++) {
            pv[i] = __ldg(p + (size_t)i * DTOT + d);
            tv[i] = __ldg(t + (size_t)i * DTOT + d);
        }
#pragma unroll
        for (int j = 0; j < 8; j++) tn[j] = fmaf(tv[j], tv[j], tn[j]);
#pragma unroll
        for (int i = 0; i < 8; i++)
#pragma unroll
            for (int j = 0; j < 8; j++)
                dacc[i][j] = fmaf(pv[i], tv[j], dacc[i][j]);
    }
    __shared__ float red[8][72];
    const int lane = tid & 31, warp = tid >> 5;
#pragma unroll
    for (int i = 0; i < 8; i++)
#pragma unroll
        for (int j = 0; j < 8; j++) {
            float v = dacc[i][j];
#pragma unroll
            for (int s = 16; s; s >>= 1) v += __shfl_xor_sync(0xFFFFFFFFu, v, s);
            if (lane == 0) red[warp][i*8+j] = v;
        }
#pragma unroll
    for (int j = 0; j < 8; j++) {
        float v = tn[j];
#pragma unroll
        for (int s = 16; s; s >>= 1) v += __shfl_xor_sync(0xFFFFFFFFu, v, s);
        if (lane == 0) red[warp][64+j] = v;
    }
    __syncthreads();
    if (tid < 72) {
        double s = 0.0;
#pragma unroll
        for (int w = 0; w < 8; w++) s += (double)red[w][tid];
        atomicAdd(&g_acc[tid], s);
    }
}

__global__ void finalize_kernel(float* __restrict__ out) {
    if (threadIdx.x != 0 || blockIdx.x != 0) return;
    double L[8][8];
    for (int i = 0; i < 8; i++)
        for (int j = 0; j < 8; j++)
            L[i][j] = (g_acc[i*8+j] - 0.5 * g_acc[64+j]) / 64.0;
    double ce = 0.0;
    for (int i = 0; i < 8; i++) {
        double m = L[i][0];
        for (int j = 1; j < 8; j++) m = L[i][j] > m ? L[i][j] : m;
        double s = 0.0;
        for (int j = 0; j < 8; j++) s += exp(L[i][j] - m);
        ce += (m + log(s)) - L[i][i];
    }
    ce /= 8.0;
    double loss = ce * (2.0 * 64.0 / 8.0) * 2e-05;
    out[0] = (float)loss;
}

// =====================================================================
extern "C" void kernel_launch(void* const* d_in, const int* in_sizes, int n_in,
                              void* d_out, int out_size) {
    const float* S  = (const float*)d_in[0];
    const float* T  = (const float*)d_in[1];
    const float* Wa = (const float*)d_in[2];
    const float* ba = (const float*)d_in[3];
    const float* W1 = (const float*)d_in[4];
    const float* b1 = (const float*)d_in[5];
    const float* W2 = (const float*)d_in[6];
    const float* b2 = (const float*)d_in[7];
    float* out = (float*)d_out;

    float* tbuf;
    cudaGetSymbolAddress((void**)&tbuf, g_t);
    __nv_bfloat16 *waH, *waL, *w1p, *mHi, *mLo;
    char *w2q, *x1q, *x0q;
    cudaGetSymbolAddress((void**)&waH, g_WaHi);
    cudaGetSymbolAddress((void**)&waL, g_WaLo);
    cudaGetSymbolAddress((void**)&w1p, g_W1p);
    cudaGetSymbolAddress((void**)&w2q, g_W2q);
    cudaGetSymbolAddress((void**)&mHi, g_mHi);
    cudaGetSymbolAddress((void**)&mLo, g_mLo);
    cudaGetSymbolAddress((void**)&x1q, g_X1q);
    cudaGetSymbolAddress((void**)&x0q, g_X0q);

    cudaFuncSetAttribute(conv1_mma,  cudaFuncAttributeMaxDynamicSharedMemorySize, 65536);
    cudaFuncSetAttribute(conv2_poly, cudaFuncAttributeMaxDynamicSharedMemorySize, 2 * STG);
    cudaFuncSetAttribute(conv3_imma, cudaFuncAttributeMaxDynamicSharedMemorySize, 65536);

    init_kernel<<<1, 128>>>();
    {
        int total = 256*128 + 36*32768;
        wprep_kernel<<<(total + 255) / 256, 256>>>(Wa, W1, W2);
    }
    conv1_mma <<<dim3(128, 2), 256, 65536>>>(waH, waL, ba, S, mHi, mLo);
    conv2_poly<<<256, 512, 2 * STG>>>(w1p, b1, mHi, mLo, x1q, x0q);
    conv3_imma<<<512, 512, 65536>>>(w2q, b2, x1q, x0q, tbuf);

    dot_kernel<<<DTOT / 2048, 256>>>(T, tbuf);
    finalize_kernel<<<1, 1>>>(out);
}

// round 15
// speedup vs baseline: 1.6058x; 1.6058x over previous
#include <cuda_runtime.h>
#include <cuda_bf16.h>
#include <cstdint>
#include <math.h>

#define NIMG 8
#define CS   128
#define CT   256
#define PIX  4096           // 64*64
#define DTOT (CT*PIX)       // per image

// ---- scratch (__device__ globals; no allocation allowed) ----
__device__ float g_t[(size_t)NIMG*CT*PIX];
__device__ double g_acc[72];

// conv1 output: COMPACT odd-parity pixels only, [img][kc(8)][pix2048][32ch]
__device__ __align__(16) __nv_bfloat16 g_mHi[(size_t)NIMG*8*2048*32];
__device__ __align__(16) __nv_bfloat16 g_mLo[(size_t)NIMG*8*2048*32];
// gen1 output: dense [img][kc(8)][pix4096][32ch]
__device__ __align__(16) __nv_bfloat16 g_g1Hi[(size_t)NIMG*8*4096*32];
__device__ __align__(16) __nv_bfloat16 g_g1Lo[(size_t)NIMG*8*4096*32];

// conv1 weights (row-major hi/lo)
__device__ __align__(16) __nv_bfloat16 g_WaHi[256*128], g_WaLo[256*128];
// conv2/3 weights packed: chunk = tap*4 + kc2 (36 chunks); within 32768 elems:
// r(0..4095)*8 + j ; r = hilo*2048 + khalf*256 + co(0..255)
__device__ __align__(16) __nv_bfloat16 g_W1p[36*32768];
__device__ __align__(16) __nv_bfloat16 g_W2p[36*32768];

// =====================================================================
// helpers (sm_80+ baseline PTX)
// =====================================================================
__device__ __forceinline__ uint32_t smem_u32(const void* p) {
    uint32_t a;
    asm("{ .reg .u64 t; cvta.to.shared.u64 t, %1; cvt.u32.u64 %0, t; }" : "=r"(a) : "l"(p));
    return a;
}
__device__ __forceinline__ void ldsm4(uint32_t* r, uint32_t addr) {
    asm volatile("ldmatrix.sync.aligned.m8n8.x4.shared.b16 {%0,%1,%2,%3}, [%4];"
                 : "=r"(r[0]), "=r"(r[1]), "=r"(r[2]), "=r"(r[3]) : "r"(addr));
}
__device__ __forceinline__ void mma16816(float* c, const uint32_t* a, uint32_t b0, uint32_t b1) {
    asm volatile("mma.sync.aligned.m16n8k16.row.col.f32.bf16.bf16.f32 "
                 "{%0,%1,%2,%3}, {%4,%5,%6,%7}, {%8,%9}, {%0,%1,%2,%3};"
                 : "+f"(c[0]), "+f"(c[1]), "+f"(c[2]), "+f"(c[3])
                 : "r"(a[0]), "r"(a[1]), "r"(a[2]), "r"(a[3]), "r"(b0), "r"(b1));
}
__device__ __forceinline__ void cp16(uint32_t dst, const void* src, uint32_t sz) {
    asm volatile("cp.async.cg.shared.global [%0], [%1], 16, %2;"
                 :: "r"(dst), "l"(src), "r"(sz) : "memory");
}
__device__ __forceinline__ void cp_commit() {
    asm volatile("cp.async.commit_group;" ::: "memory");
}
__device__ __forceinline__ void cp_wait1() {
    asm volatile("cp.async.wait_group 1;" ::: "memory");
}
__device__ __forceinline__ void bf16split(float v, __nv_bfloat16& h, __nv_bfloat16& l) {
    h = __float2bfloat16(v);
    l = __float2bfloat16(v - __bfloat162float(h));
}

// =====================================================================
// Weight prep
// =====================================================================
__global__ void wprep_kernel(const float* __restrict__ Wa, const float* __restrict__ W1,
                             const float* __restrict__ W2) {
    int t = blockIdx.x * blockDim.x + threadIdx.x;
    if (t < 256*128) {
        float v = Wa[t];
        __nv_bfloat16 h, l;
        bf16split(v, h, l);
        g_WaHi[t] = h; g_WaLo[t] = l;
    }
    int u = t - 256*128;
    if (u >= 0 && u < 36*32768) {
        int chunk  = u >> 15;
        int within = u & 32767;
        int r = within >> 3, j = within & 7;
        int tap = chunk >> 2;
        int kc2 = chunk & 3;
        int hilo  = r >> 11;
        int khalf = (r >> 8) & 7;
        int co    = r & 255;
        int ci    = kc2 * 64 + khalf * 8 + j;
        int src   = co * 2304 + ci * 9 + tap;
        {
            __nv_bfloat16 h, l;
            bf16split(W1[src], h, l);
            g_W1p[u] = hilo ? l : h;
        }
        {
            __nv_bfloat16 h, l;
            bf16split(W2[src], h, l);
            g_W2p[u] = hilo ? l : h;
        }
    }
}

__global__ void init_kernel() {
    if (threadIdx.x < 72) g_acc[threadIdx.x] = 0.0;
}

// =====================================================================
// conv1 (1x1, K=128): odd-parity pixels only (verified).
// =====================================================================
__global__ __launch_bounds__(256, 2)
void conv1_mma(const __nv_bfloat16* __restrict__ Whi, const __nv_bfloat16* __restrict__ Wlo,
               const float* __restrict__ bias, const float* __restrict__ in,
               __nv_bfloat16* __restrict__ outHi, __nv_bfloat16* __restrict__ outLo) {
    extern __shared__ char sm[];
    const int tid  = threadIdx.x;
    const int lane = tid & 31, wid = tid >> 5;
    const int m0   = blockIdx.y * 128;
    const int bx   = blockIdx.x;
    const int img  = bx >> 4;
    const int pix0 = (bx & 15) * 128;
    const float* inImg = in + (size_t)img * CS * PIX;

    constexpr int NCH = CS / 32;  // 4

    const int a_row = tid >> 1;
    const int a_k0  = (tid & 1) * 16;
    const int b_n   = tid & 127;
    const int b_sg  = tid >> 7;
    const int cpx  = pix0 + b_n;
    const int ch_h = cpx >> 5;
    const int ch_w = 2 * (cpx & 31) + ((ch_h + 1) & 1);
    const int bsrc = ch_h * 64 + ch_w;

    uint4 rAh[2], rAl[2];
    float rB[16];

    auto ldg_chunk = [&](int it) {
        const int c0 = it * 32;
        size_t aoff = (size_t)(m0 + a_row) * CS + c0 + a_k0;
        rAh[0] = *(const uint4*)(Whi + aoff);
        rAh[1] = *(const uint4*)(Whi + aoff + 8);
        rAl[0] = *(const uint4*)(Wlo + aoff);
        rAl[1] = *(const uint4*)(Wlo + aoff + 8);
        const float* p = inImg + (size_t)(c0 + b_sg * 16) * PIX + bsrc;
#pragma unroll
        for (int q = 0; q < 16; q++)
            rB[q] = __ldg(p + (size_t)q * PIX);
    };

    auto sts_chunk = [&](int s) {
        char* Ahi = sm + s * 32768;
        char* Alo = Ahi + 8192;
        char* Bhi = Ahi + 16384;
        char* Blo = Ahi + 24576;
        const int kh0 = a_k0 >> 3;
        *(uint4*)(Ahi + (kh0    ) * 2048 + a_row * 16) = rAh[0];
        *(uint4*)(Ahi + (kh0 + 1) * 2048 + a_row * 16) = rAh[1];
        *(uint4*)(Alo + (kh0    ) * 2048 + a_row * 16) = rAl[0];
        *(uint4*)(Alo + (kh0 + 1) * 2048 + a_row * 16) = rAl[1];
#pragma unroll
        for (int g = 0; g < 2; g++) {
            uint32_t hp[4], lp[4];
#pragma unroll
            for (int jp = 0; jp < 4; jp++) {
                float x0 = rB[g * 8 + 2 * jp], x1 = rB[g * 8 + 2 * jp + 1];
                __nv_bfloat16 hb0, lb0, hb1, lb1;
                bf16split(x0, hb0, lb0);
                bf16split(x1, hb1, lb1);
                hp[jp] = (uint32_t)__bfloat16_as_ushort(hb0)
                       | ((uint32_t)__bfloat16_as_ushort(hb1) << 16);
                lp[jp] = (uint32_t)__bfloat16_as_ushort(lb0)
                       | ((uint32_t)__bfloat16_as_ushort(lb1) << 16);
            }
            const int kh = b_sg * 2 + g;
            *(uint4*)(Bhi + kh * 2048 + b_n * 16) = make_uint4(hp[0], hp[1], hp[2], hp[3]);
            *(uint4*)(Blo + kh * 2048 + b_n * 16) = make_uint4(lp[0], lp[1], lp[2], lp[3]);
        }
    };

    float acc[4][4][4];
#pragma unroll
    for (int i = 0; i < 4; i++)
#pragma unroll
        for (int j = 0; j < 4; j++)
#pragma unroll
            for (int k = 0; k < 4; k++) acc[i][j][k] = 0.f;

    const int warp_m = wid & 1;
    const int warp_n = wid >> 1;
    const uint32_t smem0 = smem_u32(sm);
    const int lrow = (lane & 7) + ((lane >> 3) & 1) * 8;
    const int lkh  = (lane >> 4);

    ldg_chunk(0);
    sts_chunk(0);
    __syncthreads();

    for (int it = 0; it < NCH; ++it) {
        if (it + 1 < NCH) ldg_chunk(it + 1);
        const uint32_t S = smem0 + (it & 1) * 32768;
#pragma unroll
        for (int k16 = 0; k16 < 2; ++k16) {
            const uint32_t kbase = S + (k16 * 2 + lkh) * 2048;
            uint32_t bh[2][4], bl[2][4];
#pragma unroll
            for (int ng = 0; ng < 2; ++ng) {
                const uint32_t bd = kbase + 16384 + (warp_n * 32 + ng * 16 + lrow) * 16;
                ldsm4(bh[ng], bd);
                ldsm4(bl[ng], bd + 8192);
            }
#pragma unroll
            for (int mt = 0; mt < 4; ++mt) {
                uint32_t ah[4], al[4];
                const uint32_t ad = kbase + (warp_m * 64 + mt * 16 + lrow) * 16;
                ldsm4(ah, ad);
                ldsm4(al, ad + 8192);
#pragma unroll
                for (int nt = 0; nt < 4; ++nt)
                    mma16816(acc[mt][nt], ah, bh[nt >> 1][nt & 1], bh[nt >> 1][2 + (nt & 1)]);
#pragma unroll
                for (int nt = 0; nt < 4; ++nt)
                    mma16816(acc[mt][nt], ah, bl[nt >> 1][nt & 1], bl[nt >> 1][2 + (nt & 1)]);
#pragma unroll
                for (int nt = 0; nt < 4; ++nt)
                    mma16816(acc[mt][nt], al, bh[nt >> 1][nt & 1], bh[nt >> 1][2 + (nt & 1)]);
            }
        }
        if (it + 1 < NCH) sts_chunk((it + 1) & 1);
        __syncthreads();
    }

    const int l4 = lane >> 2, l2 = lane & 3;
    const size_t imgbase = (size_t)img * 8 * 2048 * 32;
#pragma unroll
    for (int mt = 0; mt < 4; ++mt) {
        const int co0 = m0 + warp_m * 64 + mt * 16 + l4;
        const float bi0 = bias[co0], bi1 = bias[co0 + 8];
#pragma unroll
        for (int nt = 0; nt < 4; ++nt) {
            const int p = pix0 + warp_n * 32 + nt * 8 + l2 * 2;
            float v0 = acc[mt][nt][0] + bi0;
            float v1 = acc[mt][nt][1] + bi0;
            float v2 = acc[mt][nt][2] + bi1;
            float v3 = acc[mt][nt][3] + bi1;
            const size_t o00 = imgbase + ((size_t)(co0 >> 5) * 2048 + p) * 32 + (co0 & 31);
            const size_t o10 = imgbase + ((size_t)((co0 + 8) >> 5) * 2048 + p) * 32 + ((co0 + 8) & 31);
            __nv_bfloat16 h, l;
            bf16split(v0, h, l); outHi[o00]      = h; outLo[o00]      = l;
            bf16split(v1, h, l); outHi[o00 + 32] = h; outLo[o00 + 32] = l;
            bf16split(v2, h, l); outHi[o10]      = h; outLo[o10]      = l;
            bf16split(v3, h, l); outHi[o10 + 32] = h; outLo[o10 + 32] = l;
        }
    }
}

// =====================================================================
// Shared 512-thread low-register conv core: CTA 128co x 128px, BK=64.
// Stage (64KB): A 32KB [hilo][khalf8][co128]x16B @+0,
//               B 32KB [hilo][khalf8][px128]x16B @+32768. 2 stages.
// 16 warps, warp tile 32co x 32px -> acc = 32 regs (NO SPILL).
// =====================================================================
#define STG 65536

// One k16 slice: 4 B-ldsm + 4 A-ldsm + 24 MMAs (pass-major).
#define K16_BODY(kbA, kbB)                                                          \
    {                                                                               \
        uint32_t bh[2][4], bl[2][4], ah[2][4], al[2][4];                            \
        _Pragma("unroll")                                                           \
        for (int ng = 0; ng < 2; ++ng) {                                            \
            const uint32_t bd = (kbB) + (warp_n * 32 + ng * 16 + lrow) * 16;        \
            ldsm4(bh[ng], bd);                                                      \
            ldsm4(bl[ng], bd + 16384);                                              \
        }                                                                           \
        _Pragma("unroll")                                                           \
        for (int mt = 0; mt < 2; ++mt) {                                            \
            const uint32_t ad = (kbA) + (warp_m * 32 + mt * 16 + lrow) * 16;        \
            ldsm4(ah[mt], ad);                                                      \
            ldsm4(al[mt], ad + 16384);                                              \
        }                                                                           \
        _Pragma("unroll")                                                           \
        for (int mt = 0; mt < 2; ++mt)                                              \
            _Pragma("unroll")                                                       \
            for (int nt = 0; nt < 4; ++nt)                                          \
                mma16816(acc[mt][nt], ah[mt],                                       \
                         bh[nt >> 1][nt & 1], bh[nt >> 1][2 + (nt & 1)]);           \
        _Pragma("unroll")                                                           \
        for (int mt = 0; mt < 2; ++mt)                                              \
            _Pragma("unroll")                                                       \
            for (int nt = 0; nt < 4; ++nt)                                          \
                mma16816(acc[mt][nt], ah[mt],                                       \
                         bl[nt >> 1][nt & 1], bl[nt >> 1][2 + (nt & 1)]);           \
        _Pragma("unroll")                                                           \
        for (int mt = 0; mt < 2; ++mt)                                              \
            _Pragma("unroll")                                                       \
            for (int nt = 0; nt < 4; ++nt)                                          \
                mma16816(acc[mt][nt], al[mt],                                       \
                         bh[nt >> 1][nt & 1], bh[nt >> 1][2 + (nt & 1)]);           \
    }

// conv2 (gen1, polyphase): grid (256, 2) = (img*32+P*16+htile, mb). 512 thr.
__global__ __launch_bounds__(512, 1)
void conv2_poly(const __nv_bfloat16* __restrict__ Wp,
                const float* __restrict__ bias,
                const __nv_bfloat16* __restrict__ actHi,
                const __nv_bfloat16* __restrict__ actLo,
                __nv_bfloat16* __restrict__ outHi,
                __nv_bfloat16* __restrict__ outLo) {
    extern __shared__ char sm[];
    const int tid  = threadIdx.x;
    const int lane = tid & 31, wid = tid >> 5;
    const int mb   = blockIdx.y;
    const int bx   = blockIdx.x;
    const int img  = bx >> 5;
    const int rem  = bx & 31;
    const int P    = rem >> 4;
    const int h0   = (rem & 15) * 4;

    const int NT  = 4 + P;
    const int NCH = NT * 4;
    const uint32_t smem0 = smem_u32(sm);

    // A producer: 4 rows, chunk-relative element offsets (constant)
    uint32_t aRow[4];
#pragma unroll
    for (int i = 0; i < 4; ++i) {
        const int br = tid + 512 * i;
        const int hilo = br >> 10, khalf = (br >> 7) & 7, co = br & 127;
        aRow[i] = (uint32_t)(hilo * 2048 + khalf * 256 + mb * 128 + co) * 8;
    }
    const uint32_t dstA0 = smem0 + tid * 16;
    const uint32_t dstB0 = smem0 + 32768 + tid * 16;
    // B geometry: single (px) per thread; kh0 = tid>>7 in 0..3
    const int bpx = tid & 127;
    const int bkh = tid >> 7;      // 0..3

    const __nv_bfloat16* aPtr = Wp;
    uint32_t bOff = 0, bOkSz = 0;

    auto setup_tap = [&](int tap_t) {
        const int tapid = P ? (2 * tap_t) : (2 * tap_t + 1);
        const int dh = tapid / 3 - 1, dw = tapid % 3 - 1;
        aPtr = Wp + (size_t)tapid * 4 * 32768;
        const int row = h0 + (bpx >> 5);
        const int ow  = 2 * (bpx & 31) + ((P + row) & 1);
        const int h = row + dh, w = ow + dw;
        const bool ok = ((unsigned)h < 64u) & ((unsigned)w < 64u);
        const int ci = ok ? ((w - ((h + 1) & 1)) >> 1) : 0;
        const int hpix = ok ? (h * 32 + ci) : 0;
        bOff = ((uint32_t)(img * 8) * 2048 + hpix) * 32 + bkh * 8;
        bOkSz = ok ? 16u : 0u;
    };

    auto issue = [&](int it) {
        const uint32_t sb = (uint32_t)(it & 1) * STG;
        const int kc2 = it & 3;
        if (kc2 == 0) setup_tap(it >> 2);
        const __nv_bfloat16* a = aPtr + kc2 * 32768;
#pragma unroll
        for (int i = 0; i < 4; ++i)
            cp16(dstA0 + sb + 8192u * i, a + aRow[i], 16u);
        const uint32_t base = bOff + (uint32_t)kc2 * 131072u;  // kc = kc2*2
        cp16(dstB0 + sb,         actHi + base,          bOkSz);
        cp16(dstB0 + sb + 8192,  actHi + base + 65536,  bOkSz);   // kc+1 plane
        cp16(dstB0 + sb + 16384, actLo + base,          bOkSz);
        cp16(dstB0 + sb + 24576, actLo + base + 65536,  bOkSz);
    };

    float acc[2][4][4];
#pragma unroll
    for (int i = 0; i < 2; i++)
#pragma unroll
        for (int j = 0; j < 4; j++)
#pragma unroll
            for (int k = 0; k < 4; k++) acc[i][j][k] = 0.f;

    const int warp_m = wid >> 2;   // 0..3 -> 32 co each
    const int warp_n = wid & 3;    // 0..3 -> 32 px each
    const int lrow = (lane & 7) + ((lane >> 3) & 1) * 8;
    const int lkh  = (lane >> 4);

    issue(0); cp_commit();

    for (int it = 0; it < NCH; ++it) {
        if (it + 1 < NCH) issue(it + 1);
        cp_commit();
        cp_wait1();
        __syncthreads();

        const uint32_t S = smem0 + (it & 1) * STG;
#pragma unroll
        for (int k16 = 0; k16 < 4; ++k16) {
            const int khl = k16 * 2 + lkh;
            const uint32_t kbA = S + khl * 2048;
            const uint32_t kbB = S + 32768 + khl * 2048;
            K16_BODY(kbA, kbB)
        }
        __syncthreads();
    }

    // epilogue: bias + relu, scatter to dense hi/lo planes
    const int l4 = lane >> 2, l2 = lane & 3;
    const int row = h0 + warp_n;
    const int wpar = (P + row) & 1;
    const size_t imgbase = (size_t)img * 8 * 4096 * 32;
#pragma unroll
    for (int mt = 0; mt < 2; ++mt) {
        const int co0 = mb * 128 + warp_m * 32 + mt * 16 + l4;
        const float bi0 = bias[co0], bi1 = bias[co0 + 8];
        const size_t cb0 = imgbase + (size_t)(co0 >> 5) * 4096 * 32 + (co0 & 31);
        const size_t cb1 = imgbase + (size_t)((co0 + 8) >> 5) * 4096 * 32 + ((co0 + 8) & 31);
#pragma unroll
        for (int nt = 0; nt < 4; ++nt) {
            const int j0 = nt * 8 + l2 * 2;
            const int pix0e = row * 64 + 2 * j0 + wpar;
            const int pix1e = pix0e + 2;
            float v0 = fmaxf(acc[mt][nt][0] + bi0, 0.f);
            float v1 = fmaxf(acc[mt][nt][1] + bi0, 0.f);
            float v2 = fmaxf(acc[mt][nt][2] + bi1, 0.f);
            float v3 = fmaxf(acc[mt][nt][3] + bi1, 0.f);
            __nv_bfloat16 h, l;
            bf16split(v0, h, l); outHi[cb0 + (size_t)pix0e * 32] = h; outLo[cb0 + (size_t)pix0e * 32] = l;
            bf16split(v1, h, l); outHi[cb0 + (size_t)pix1e * 32] = h; outLo[cb0 + (size_t)pix1e * 32] = l;
            bf16split(v2, h, l); outHi[cb1 + (size_t)pix0e * 32] = h; outLo[cb1 + (size_t)pix0e * 32] = l;
            bf16split(v3, h, l); outHi[cb1 + (size_t)pix1e * 32] = h; outLo[cb1 + (size_t)pix1e * 32] = l;
        }
    }
}

// conv3 (dense 3x3): grid (256, 2) = (img*32+pixtile, mb). 512 thr, fp32 out.
__global__ __launch_bounds__(512, 1)
void conv3_cp(const __nv_bfloat16* __restrict__ Wp,
              const float* __restrict__ bias,
              const __nv_bfloat16* __restrict__ actHi,
              const __nv_bfloat16* __restrict__ actLo,
              float* __restrict__ outF32) {
    extern __shared__ char sm[];
    const int tid  = threadIdx.x;
    const int lane = tid & 31, wid = tid >> 5;
    const int mb   = blockIdx.y;
    const int bx   = blockIdx.x;
    const int img  = bx >> 5;
    const int pix0 = (bx & 31) * 128;
    const int h0   = pix0 >> 6;

    constexpr int NCH = 36;
    const uint32_t smem0 = smem_u32(sm);

    uint32_t aRow[4];
#pragma unroll
    for (int i = 0; i < 4; ++i) {
        const int br = tid + 512 * i;
        const int hilo = br >> 10, khalf = (br >> 7) & 7, co = br & 127;
        aRow[i] = (uint32_t)(hilo * 2048 + khalf * 256 + mb * 128 + co) * 8;
    }
    const uint32_t dstA0 = smem0 + tid * 16;
    const uint32_t dstB0 = smem0 + 32768 + tid * 16;
    const int bpx = tid & 127;
    const int bkh = tid >> 7;

    const __nv_bfloat16* aPtr = Wp;
    uint32_t bOff = 0, bOkSz = 0;

    auto setup_tap = [&](int tap) {
        const int dh = tap / 3 - 1, dw = tap % 3 - 1;
        aPtr = Wp + (size_t)tap * 4 * 32768;
        const int h = h0 + (bpx >> 6) + dh, w = (bpx & 63) + dw;
        const bool ok = ((unsigned)h < 64u) & ((unsigned)w < 64u);
        const int hpix = ok ? (h * 64 + w) : 0;
        bOff = ((uint32_t)(img * 8) * 4096 + hpix) * 32 + bkh * 8;
        bOkSz = ok ? 16u : 0u;
    };

    auto issue = [&](int it) {
        const uint32_t sb = (uint32_t)(it & 1) * STG;
        const int kc2 = it & 3;
        if (kc2 == 0) setup_tap(it >> 2);
        const __nv_bfloat16* a = aPtr + kc2 * 32768;
#pragma unroll
        for (int i = 0; i < 4; ++i)
            cp16(dstA0 + sb + 8192u * i, a + aRow[i], 16u);
        const uint32_t base = bOff + (uint32_t)kc2 * 262144u;
        cp16(dstB0 + sb,         actHi + base,           bOkSz);
        cp16(dstB0 + sb + 8192,  actHi + base + 131072,  bOkSz);
        cp16(dstB0 + sb + 16384, actLo + base,           bOkSz);
        cp16(dstB0 + sb + 24576, actLo + base + 131072,  bOkSz);
    };

    float acc[2][4][4];
#pragma unroll
    for (int i = 0; i < 2; i++)
#pragma unroll
        for (int j = 0; j < 4; j++)
#pragma unroll
            for (int k = 0; k < 4; k++) acc[i][j][k] = 0.f;

    const int warp_m = wid >> 2;
    const int warp_n = wid & 3;
    const int lrow = (lane & 7) + ((lane >> 3) & 1) * 8;
    const int lkh  = (lane >> 4);

    issue(0); cp_commit();

    for (int it = 0; it < NCH; ++it) {
        if (it + 1 < NCH) issue(it + 1);
        cp_commit();
        cp_wait1();
        __syncthreads();

        const uint32_t S = smem0 + (it & 1) * STG;
#pragma unroll
        for (int k16 = 0; k16 < 4; ++k16) {
            const int khl = k16 * 2 + lkh;
            const uint32_t kbA = S + khl * 2048;
            const uint32_t kbB = S + 32768 + khl * 2048;
            K16_BODY(kbA, kbB)
        }
        __syncthreads();
    }

    const int l4 = lane >> 2, l2 = lane & 3;
    float* outImg = outF32 + (size_t)img * CT * PIX;
#pragma unroll
    for (int mt = 0; mt < 2; ++mt) {
        const int co0 = mb * 128 + warp_m * 32 + mt * 16 + l4;
        const float bi0 = bias[co0], bi1 = bias[co0 + 8];
#pragma unroll
        for (int nt = 0; nt < 4; ++nt) {
            const int p = pix0 + warp_n * 32 + nt * 8 + l2 * 2;
            float v0 = acc[mt][nt][0] + bi0;
            float v1 = acc[mt][nt][1] + bi0;
            float v2 = acc[mt][nt][2] + bi1;
            float v3 = acc[mt][nt][3] + bi1;
            *(float2*)(outImg + (size_t)co0 * PIX + p)       = make_float2(v0, v1);
            *(float2*)(outImg + (size_t)(co0 + 8) * PIX + p) = make_float2(v2, v3);
        }
    }
}

// =====================================================================
// pairwise dots + target norms (unchanged, verified)
// =====================================================================
__global__ __launch_bounds__(256)
void dot_kernel(const float* __restrict__ p, const float* __restrict__ t) {
    const int tid = threadIdx.x;
    const int d0  = blockIdx.x * 2048 + tid;

    float dacc[8][8];
    float tn[8];
#pragma unroll
    for (int i = 0; i < 8; i++) {
        tn[i] = 0.f;
#pragma unroll
        for (int j = 0; j < 8; j++) dacc[i][j] = 0.f;
    }
#pragma unroll 2
    for (int it = 0; it < 8; it++) {
        int d = d0 + it * 256;
        float pv[8], tv[8];
#pragma unroll
        for (int i = 0; i < 8; i++) {
            pv[i] = __ldg(p + (size_t)i * DTOT + d);
            tv[i] = __ldg(t + (size_t)i * DTOT + d);
        }
#pragma unroll
        for (int j = 0; j < 8; j++) tn[j] = fmaf(tv[j], tv[j], tn[j]);
#pragma unroll
        for (int i = 0; i < 8; i++)
#pragma unroll
            for (int j = 0; j < 8; j++)
                dacc[i][j] = fmaf(pv[i], tv[j], dacc[i][j]);
    }
    __shared__ float red[8][72];
    const int lane = tid & 31, warp = tid >> 5;
#pragma unroll
    for (int i = 0; i < 8; i++)
#pragma unroll
        for (int j = 0; j < 8; j++) {
            float v = dacc[i][j];
#pragma unroll
            for (int s = 16; s; s >>= 1) v += __shfl_xor_sync(0xFFFFFFFFu, v, s);
            if (lane == 0) red[warp][i*8+j] = v;
        }
#pragma unroll
    for (int j = 0; j < 8; j++) {
        float v = tn[j];
#pragma unroll
        for (int s = 16; s; s >>= 1) v += __shfl_xor_sync(0xFFFFFFFFu, v, s);
        if (lane == 0) red[warp][64+j] = v;
    }
    __syncthreads();
    if (tid < 72) {
        double s = 0.0;
#pragma unroll
        for (int w = 0; w < 8; w++) s += (double)red[w][tid];
        atomicAdd(&g_acc[tid], s);
    }
}

__global__ void finalize_kernel(float* __restrict__ out) {
    if (threadIdx.x != 0 || blockIdx.x != 0) return;
    double L[8][8];
    for (int i = 0; i < 8; i++)
        for (int j = 0; j < 8; j++)
            L[i][j] = (g_acc[i*8+j] - 0.5 * g_acc[64+j]) / 64.0;
    double ce = 0.0;
    for (int i = 0; i < 8; i++) {
        double m = L[i][0];
        for (int j = 1; j < 8; j++) m = L[i][j] > m ? L[i][j] : m;
        double s = 0.0;
        for (int j = 0; j < 8; j++) s += exp(L[i][j] - m);
        ce += (m + log(s)) - L[i][i];
    }
    ce /= 8.0;
    double loss = ce * (2.0 * 64.0 / 8.0) * 2e-05;
    out[0] = (float)loss;
}

// =====================================================================
extern "C" void kernel_launch(void* const* d_in, const int* in_sizes, int n_in,
                              void* d_out, int out_size) {
    const float* S  = (const float*)d_in[0];
    const float* T  = (const float*)d_in[1];
    const float* Wa = (const float*)d_in[2];
    const float* ba = (const float*)d_in[3];
    const float* W1 = (const float*)d_in[4];
    const float* b1 = (const float*)d_in[5];
    const float* W2 = (const float*)d_in[6];
    const float* b2 = (const float*)d_in[7];
    float* out = (float*)d_out;

    float* tbuf;
    cudaGetSymbolAddress((void**)&tbuf, g_t);
    __nv_bfloat16 *waH, *waL, *w1p, *w2p, *mHi, *mLo, *g1Hi, *g1Lo;
    cudaGetSymbolAddress((void**)&waH, g_WaHi);
    cudaGetSymbolAddress((void**)&waL, g_WaLo);
    cudaGetSymbolAddress((void**)&w1p, g_W1p);
    cudaGetSymbolAddress((void**)&w2p, g_W2p);
    cudaGetSymbolAddress((void**)&mHi, g_mHi);
    cudaGetSymbolAddress((void**)&mLo, g_mLo);
    cudaGetSymbolAddress((void**)&g1Hi, g_g1Hi);
    cudaGetSymbolAddress((void**)&g1Lo, g_g1Lo);

    cudaFuncSetAttribute(conv1_mma,  cudaFuncAttributeMaxDynamicSharedMemorySize, 65536);
    cudaFuncSetAttribute(conv2_poly, cudaFuncAttributeMaxDynamicSharedMemorySize, 2 * STG);
    cudaFuncSetAttribute(conv3_cp,   cudaFuncAttributeMaxDynamicSharedMemorySize, 2 * STG);

    init_kernel<<<1, 128>>>();
    {
        int total = 256*128 + 36*32768;
        wprep_kernel<<<(total + 255) / 256, 256>>>(Wa, W1, W2);
    }
    conv1_mma <<<dim3(128, 2), 256, 65536>>>(waH, waL, ba, S, mHi, mLo);
    conv2_poly<<<dim3(256, 2), 512, 2 * STG>>>(w1p, b1, mHi, mLo, g1Hi, g1Lo);
    conv3_cp  <<<dim3(256, 2), 512, 2 * STG>>>(w2p, b2, g1Hi, g1Lo, tbuf);

    dot_kernel<<<DTOT / 2048, 256>>>(T, tbuf);
    finalize_kernel<<<1, 1>>>(out);
}

// round 17
// speedup vs baseline: 2.3331x; 1.4529x over previous
#include <cuda_runtime.h>
#include <cuda_bf16.h>
#include <cuda_fp16.h>
#include <cstdint>
#include <math.h>

#define NIMG 8
#define CS   128
#define CT   256
#define PIX  4096           // 64*64
#define DTOT (CT*PIX)       // per image

// ---- scratch (__device__ globals; no allocation allowed) ----
__device__ float g_t[(size_t)NIMG*CT*PIX];
__device__ double g_acc[72];

// conv1 output: COMPACT odd-parity pixels, fp16 hi/lo [img][kc8][pix2048][32]
__device__ __align__(16) __half g_mHi[(size_t)NIMG*8*2048*32];
__device__ __align__(16) __half g_mLo[(size_t)NIMG*8*2048*32];
// gen1 output: dense fp16 hi/lo [img][kc8][pix4096][32]
__device__ __align__(16) __half g_g1Hi[(size_t)NIMG*8*4096*32];
__device__ __align__(16) __half g_g1Lo[(size_t)NIMG*8*4096*32];

// conv1 weights (row-major bf16 hi/lo; conv1 keeps bf16x3 core)
__device__ __align__(16) __nv_bfloat16 g_WaHi[256*128], g_WaLo[256*128];
// conv2/3 weights: SINGLE fp16 plane, packed: chunk = tap*4 + kc2 (36);
// within 16384 halves: r(0..2047)*8 + j ; r = khalf*256 + co(0..255)
__device__ __align__(16) __half g_W1h[36*16384];
__device__ __align__(16) __half g_W2h[36*16384];

// =====================================================================
// helpers (sm_80+ baseline PTX)
// =====================================================================
__device__ __forceinline__ uint32_t smem_u32(const void* p) {
    uint32_t a;
    asm("{ .reg .u64 t; cvta.to.shared.u64 t, %1; cvt.u32.u64 %0, t; }" : "=r"(a) : "l"(p));
    return a;
}
__device__ __forceinline__ void ldsm4(uint32_t* r, uint32_t addr) {
    asm volatile("ldmatrix.sync.aligned.m8n8.x4.shared.b16 {%0,%1,%2,%3}, [%4];"
                 : "=r"(r[0]), "=r"(r[1]), "=r"(r[2]), "=r"(r[3]) : "r"(addr));
}
__device__ __forceinline__ void mma_bf16(float* c, const uint32_t* a, uint32_t b0, uint32_t b1) {
    asm volatile("mma.sync.aligned.m16n8k16.row.col.f32.bf16.bf16.f32 "
                 "{%0,%1,%2,%3}, {%4,%5,%6,%7}, {%8,%9}, {%0,%1,%2,%3};"
                 : "+f"(c[0]), "+f"(c[1]), "+f"(c[2]), "+f"(c[3])
                 : "r"(a[0]), "r"(a[1]), "r"(a[2]), "r"(a[3]), "r"(b0), "r"(b1));
}
__device__ __forceinline__ void mma_f16(float* c, const uint32_t* a, uint32_t b0, uint32_t b1) {
    asm volatile("mma.sync.aligned.m16n8k16.row.col.f32.f16.f16.f32 "
                 "{%0,%1,%2,%3}, {%4,%5,%6,%7}, {%8,%9}, {%0,%1,%2,%3};"
                 : "+f"(c[0]), "+f"(c[1]), "+f"(c[2]), "+f"(c[3])
                 : "r"(a[0]), "r"(a[1]), "r"(a[2]), "r"(a[3]), "r"(b0), "r"(b1));
}
__device__ __forceinline__ void cp16(uint32_t dst, const void* src, uint32_t sz) {
    asm volatile("cp.async.cg.shared.global [%0], [%1], 16, %2;"
                 :: "r"(dst), "l"(src), "r"(sz) : "memory");
}
__device__ __forceinline__ void cp_commit() {
    asm volatile("cp.async.commit_group;" ::: "memory");
}
__device__ __forceinline__ void cp_wait1() {
    asm volatile("cp.async.wait_group 1;" ::: "memory");
}
__device__ __forceinline__ void bf16split(float v, __nv_bfloat16& h, __nv_bfloat16& l) {
    h = __float2bfloat16(v);
    l = __float2bfloat16(v - __bfloat162float(h));
}
__device__ __forceinline__ void f16split(float v, __half& h, __half& l) {
    h = __float2half(v);
    l = __float2half(v - __half2float(h));
}

// =====================================================================
// Weight prep
// =====================================================================
__global__ void wprep_kernel(const float* __restrict__ Wa, const float* __restrict__ W1,
                             const float* __restrict__ W2) {
    int t = blockIdx.x * blockDim.x + threadIdx.x;
    if (t < 256*128) {
        float v = Wa[t];
        __nv_bfloat16 h, l;
        bf16split(v, h, l);
        g_WaHi[t] = h; g_WaLo[t] = l;
    }
    int u = t - 256*128;
    if (u >= 0 && u < 36*16384) {
        int chunk  = u >> 14;
        int within = u & 16383;
        int r = within >> 3, j = within & 7;
        int tap = chunk >> 2;
        int kc2 = chunk & 3;
        int khalf = r >> 8;
        int co    = r & 255;
        int ci    = kc2 * 64 + khalf * 8 + j;
        int src   = co * 2304 + ci * 9 + tap;
        g_W1h[u] = __float2half(W1[src]);
        g_W2h[u] = __float2half(W2[src]);
    }
}

__global__ void init_kernel() {
    if (threadIdx.x < 72) g_acc[threadIdx.x] = 0.0;
}

// =====================================================================
// conv1 (1x1, K=128): bf16x3 core (verified), odd-parity pixels only.
// Epilogue writes fp16 hi/lo planes.
// =====================================================================
__global__ __launch_bounds__(256, 2)
void conv1_mma(const __nv_bfloat16* __restrict__ Whi, const __nv_bfloat16* __restrict__ Wlo,
               const float* __restrict__ bias, const float* __restrict__ in,
               __half* __restrict__ outHi, __half* __restrict__ outLo) {
    extern __shared__ char sm[];
    const int tid  = threadIdx.x;
    const int lane = tid & 31, wid = tid >> 5;
    const int m0   = blockIdx.y * 128;
    const int bx   = blockIdx.x;
    const int img  = bx >> 4;
    const int pix0 = (bx & 15) * 128;
    const float* inImg = in + (size_t)img * CS * PIX;

    constexpr int NCH = CS / 32;  // 4

    const int a_row = tid >> 1;
    const int a_k0  = (tid & 1) * 16;
    const int b_n   = tid & 127;
    const int b_sg  = tid >> 7;
    const int cpx  = pix0 + b_n;
    const int ch_h = cpx >> 5;
    const int ch_w = 2 * (cpx & 31) + ((ch_h + 1) & 1);
    const int bsrc = ch_h * 64 + ch_w;

    uint4 rAh[2], rAl[2];
    float rB[16];

    auto ldg_chunk = [&](int it) {
        const int c0 = it * 32;
        size_t aoff = (size_t)(m0 + a_row) * CS + c0 + a_k0;
        rAh[0] = *(const uint4*)(Whi + aoff);
        rAh[1] = *(const uint4*)(Whi + aoff + 8);
        rAl[0] = *(const uint4*)(Wlo + aoff);
        rAl[1] = *(const uint4*)(Wlo + aoff + 8);
        const float* p = inImg + (size_t)(c0 + b_sg * 16) * PIX + bsrc;
#pragma unroll
        for (int q = 0; q < 16; q++)
            rB[q] = __ldg(p + (size_t)q * PIX);
    };

    auto sts_chunk = [&](int s) {
        char* Ahi = sm + s * 32768;
        char* Alo = Ahi + 8192;
        char* Bhi = Ahi + 16384;
        char* Blo = Ahi + 24576;
        const int kh0 = a_k0 >> 3;
        *(uint4*)(Ahi + (kh0    ) * 2048 + a_row * 16) = rAh[0];
        *(uint4*)(Ahi + (kh0 + 1) * 2048 + a_row * 16) = rAh[1];
        *(uint4*)(Alo + (kh0    ) * 2048 + a_row * 16) = rAl[0];
        *(uint4*)(Alo + (kh0 + 1) * 2048 + a_row * 16) = rAl[1];
#pragma unroll
        for (int g = 0; g < 2; g++) {
            uint32_t hp[4], lp[4];
#pragma unroll
            for (int jp = 0; jp < 4; jp++) {
                float x0 = rB[g * 8 + 2 * jp], x1 = rB[g * 8 + 2 * jp + 1];
                __nv_bfloat16 hb0, lb0, hb1, lb1;
                bf16split(x0, hb0, lb0);
                bf16split(x1, hb1, lb1);
                hp[jp] = (uint32_t)__bfloat16_as_ushort(hb0)
                       | ((uint32_t)__bfloat16_as_ushort(hb1) << 16);
                lp[jp] = (uint32_t)__bfloat16_as_ushort(lb0)
                       | ((uint32_t)__bfloat16_as_ushort(lb1) << 16);
            }
            const int kh = b_sg * 2 + g;
            *(uint4*)(Bhi + kh * 2048 + b_n * 16) = make_uint4(hp[0], hp[1], hp[2], hp[3]);
            *(uint4*)(Blo + kh * 2048 + b_n * 16) = make_uint4(lp[0], lp[1], lp[2], lp[3]);
        }
    };

    float acc[4][4][4];
#pragma unroll
    for (int i = 0; i < 4; i++)
#pragma unroll
        for (int j = 0; j < 4; j++)
#pragma unroll
            for (int k = 0; k < 4; k++) acc[i][j][k] = 0.f;

    const int warp_m = wid & 1;
    const int warp_n = wid >> 1;
    const uint32_t smem0 = smem_u32(sm);
    const int lrow = (lane & 7) + ((lane >> 3) & 1) * 8;
    const int lkh  = (lane >> 4);

    ldg_chunk(0);
    sts_chunk(0);
    __syncthreads();

    for (int it = 0; it < NCH; ++it) {
        if (it + 1 < NCH) ldg_chunk(it + 1);
        const uint32_t S = smem0 + (it & 1) * 32768;
#pragma unroll
        for (int k16 = 0; k16 < 2; ++k16) {
            const uint32_t kbase = S + (k16 * 2 + lkh) * 2048;
            uint32_t bh[2][4], bl[2][4];
#pragma unroll
            for (int ng = 0; ng < 2; ++ng) {
                const uint32_t bd = kbase + 16384 + (warp_n * 32 + ng * 16 + lrow) * 16;
                ldsm4(bh[ng], bd);
                ldsm4(bl[ng], bd + 8192);
            }
#pragma unroll
            for (int mt = 0; mt < 4; ++mt) {
                uint32_t ah[4], al[4];
                const uint32_t ad = kbase + (warp_m * 64 + mt * 16 + lrow) * 16;
                ldsm4(ah, ad);
                ldsm4(al, ad + 8192);
#pragma unroll
                for (int nt = 0; nt < 4; ++nt)
                    mma_bf16(acc[mt][nt], ah, bh[nt >> 1][nt & 1], bh[nt >> 1][2 + (nt & 1)]);
#pragma unroll
                for (int nt = 0; nt < 4; ++nt)
                    mma_bf16(acc[mt][nt], ah, bl[nt >> 1][nt & 1], bl[nt >> 1][2 + (nt & 1)]);
#pragma unroll
                for (int nt = 0; nt < 4; ++nt)
                    mma_bf16(acc[mt][nt], al, bh[nt >> 1][nt & 1], bh[nt >> 1][2 + (nt & 1)]);
            }
        }
        if (it + 1 < NCH) sts_chunk((it + 1) & 1);
        __syncthreads();
    }

    const int l4 = lane >> 2, l2 = lane & 3;
    const size_t imgbase = (size_t)img * 8 * 2048 * 32;
#pragma unroll
    for (int mt = 0; mt < 4; ++mt) {
        const int co0 = m0 + warp_m * 64 + mt * 16 + l4;
        const float bi0 = bias[co0], bi1 = bias[co0 + 8];
#pragma unroll
        for (int nt = 0; nt < 4; ++nt) {
            const int p = pix0 + warp_n * 32 + nt * 8 + l2 * 2;
            float v0 = acc[mt][nt][0] + bi0;
            float v1 = acc[mt][nt][1] + bi0;
            float v2 = acc[mt][nt][2] + bi1;
            float v3 = acc[mt][nt][3] + bi1;
            const size_t o00 = imgbase + ((size_t)(co0 >> 5) * 2048 + p) * 32 + (co0 & 31);
            const size_t o10 = imgbase + ((size_t)((co0 + 8) >> 5) * 2048 + p) * 32 + ((co0 + 8) & 31);
            __half h, l;
            f16split(v0, h, l); outHi[o00]      = h; outLo[o00]      = l;
            f16split(v1, h, l); outHi[o00 + 32] = h; outLo[o00 + 32] = l;
            f16split(v2, h, l); outHi[o10]      = h; outLo[o10]      = l;
            f16split(v3, h, l); outHi[o10 + 32] = h; outLo[o10 + 32] = l;
        }
    }
}

// =====================================================================
// Shared 512-thread fp16x2 conv core: CTA 256co x 128px, BK=64.
// Stage (64KB): A 32KB single fp16 plane [khalf8][co256]x16B @+0,
//               B 32KB fp16 hi/lo [plane2][khalf8][px128]x16B @+32768.
// 2 stages (128KB). Consumer: per-mt A ldsm, 2 passes (hi, lo).
// =====================================================================
#define STG 65536

#define K16_BODY_F16(kbA, kbB)                                                      \
    {                                                                               \
        uint32_t bh[2][4], bl[2][4];                                                \
        _Pragma("unroll")                                                           \
        for (int ng = 0; ng < 2; ++ng) {                                            \
            const uint32_t bd = (kbB) + (warp_n * 32 + ng * 16 + lrow) * 16;        \
            ldsm4(bh[ng], bd);                                                      \
            ldsm4(bl[ng], bd + 16384);                                              \
        }                                                                           \
        _Pragma("unroll")                                                           \
        for (int mt = 0; mt < 4; ++mt) {                                            \
            uint32_t a[4];                                                          \
            ldsm4(a, (kbA) + (warp_m * 64 + mt * 16 + lrow) * 16);                  \
            _Pragma("unroll")                                                       \
            for (int nt = 0; nt < 4; ++nt)                                          \
                mma_f16(acc[mt][nt], a,                                             \
                        bh[nt >> 1][nt & 1], bh[nt >> 1][2 + (nt & 1)]);            \
            _Pragma("unroll")                                                       \
            for (int nt = 0; nt < 4; ++nt)                                          \
                mma_f16(acc[mt][nt], a,                                             \
                        bl[nt >> 1][nt & 1], bl[nt >> 1][2 + (nt & 1)]);            \
        }                                                                           \
    }

// conv2 (gen1, polyphase): grid 256 = img*32 + P*16 + htile. 512 thr.
__global__ __launch_bounds__(512, 1)
void conv2_poly(const __half* __restrict__ Wp,
                const float* __restrict__ bias,
                const __half* __restrict__ actHi,
                const __half* __restrict__ actLo,
                __half* __restrict__ outHi,
                __half* __restrict__ outLo) {
    extern __shared__ char sm[];
    const int tid  = threadIdx.x;
    const int lane = tid & 31, wid = tid >> 5;
    const int bx   = blockIdx.x;
    const int img  = bx >> 5;
    const int rem  = bx & 31;
    const int P    = rem >> 4;
    const int h0   = (rem & 15) * 4;

    const int NT  = 4 + P;
    const int NCH = NT * 4;
    const uint32_t smem0 = smem_u32(sm);
    const uint32_t dstA0 = smem0 + tid * 16;
    const uint32_t dstB0 = smem0 + 32768 + tid * 16;
    const int bpx = tid & 127;   // pixel this thread loads
    const int bch = tid >> 7;    // channel-group 0..3 -> (bch*8) within kc

    const __half* aPtr = Wp;
    uint32_t bOff = 0, bOkSz = 0;

    auto setup_tap = [&](int tap_t) {
        const int tapid = P ? (2 * tap_t) : (2 * tap_t + 1);
        const int dh = tapid / 3 - 1, dw = tapid % 3 - 1;
        aPtr = Wp + (size_t)tapid * 4 * 16384 + tid * 8;
        const int row = h0 + (bpx >> 5);
        const int ow  = 2 * (bpx & 31) + ((P + row) & 1);
        const int h = row + dh, w = ow + dw;
        const bool ok = ((unsigned)h < 64u) & ((unsigned)w < 64u);
        const int ci = ok ? ((w - ((h + 1) & 1)) >> 1) : 0;
        const int hpix = ok ? (h * 32 + ci) : 0;
        bOff = ((uint32_t)(img * 8) * 2048 + hpix) * 32 + bch * 8;
        bOkSz = ok ? 16u : 0u;
    };

    auto issue = [&](int it) {
        const uint32_t sb = (uint32_t)(it & 1) * STG;
        const int kc2 = it & 3;
        if (kc2 == 0) setup_tap(it >> 2);
        const __half* a = aPtr + kc2 * 16384;
#pragma unroll
        for (int i = 0; i < 4; ++i)
            cp16(dstA0 + sb + 8192u * i, a + 4096 * i, 16u);
        const uint32_t base = bOff + (uint32_t)kc2 * 131072u;   // kc = 2*kc2
        cp16(dstB0 + sb,         actHi + base,          bOkSz); // kc even, hi
        cp16(dstB0 + sb + 8192,  actHi + base + 65536,  bOkSz); // kc odd,  hi
        cp16(dstB0 + sb + 16384, actLo + base,          bOkSz); // kc even, lo
        cp16(dstB0 + sb + 24576, actLo + base + 65536,  bOkSz); // kc odd,  lo
    };

    float acc[4][4][4];
#pragma unroll
    for (int i = 0; i < 4; i++)
#pragma unroll
        for (int j = 0; j < 4; j++)
#pragma unroll
            for (int k = 0; k < 4; k++) acc[i][j][k] = 0.f;

    const int warp_m = wid >> 2;   // 0..3 -> 64 co each
    const int warp_n = wid & 3;    // 0..3 -> 32 px each
    const int lrow = (lane & 7) + ((lane >> 3) & 1) * 8;
    const int lkh  = (lane >> 4);

    issue(0); cp_commit();

    for (int it = 0; it < NCH; ++it) {
        if (it + 1 < NCH) issue(it + 1);
        cp_commit();
        cp_wait1();
        __syncthreads();

        const uint32_t S = smem0 + (it & 1) * STG;
#pragma unroll
        for (int k16 = 0; k16 < 4; ++k16) {
            const int khl = k16 * 2 + lkh;
            const uint32_t kbA = S + khl * 4096;
            const uint32_t kbB = S + 32768 + khl * 2048;
            K16_BODY_F16(kbA, kbB)
        }
        __syncthreads();
    }

    // epilogue: bias + relu, scatter to dense fp16 hi/lo planes
    const int l4 = lane >> 2, l2 = lane & 3;
    const int row = h0 + warp_n;
    const int wpar = (P + row) & 1;
    const size_t imgbase = (size_t)img * 8 * 4096 * 32;
#pragma unroll
    for (int mt = 0; mt < 4; ++mt) {
        const int co0 = warp_m * 64 + mt * 16 + l4;
        const float bi0 = bias[co0], bi1 = bias[co0 + 8];
        const size_t cb0 = imgbase + (size_t)(co0 >> 5) * 4096 * 32 + (co0 & 31);
        const size_t cb1 = imgbase + (size_t)((co0 + 8) >> 5) * 4096 * 32 + ((co0 + 8) & 31);
#pragma unroll
        for (int nt = 0; nt < 4; ++nt) {
            const int j0 = nt * 8 + l2 * 2;
            const int pix0e = row * 64 + 2 * j0 + wpar;
            const int pix1e = pix0e + 2;
            float v0 = fmaxf(acc[mt][nt][0] + bi0, 0.f);
            float v1 = fmaxf(acc[mt][nt][1] + bi0, 0.f);
            float v2 = fmaxf(acc[mt][nt][2] + bi1, 0.f);
            float v3 = fmaxf(acc[mt][nt][3] + bi1, 0.f);
            __half h, l;
            f16split(v0, h, l); outHi[cb0 + (size_t)pix0e * 32] = h; outLo[cb0 + (size_t)pix0e * 32] = l;
            f16split(v1, h, l); outHi[cb0 + (size_t)pix1e * 32] = h; outLo[cb0 + (size_t)pix1e * 32] = l;
            f16split(v2, h, l); outHi[cb1 + (size_t)pix0e * 32] = h; outLo[cb1 + (size_t)pix0e * 32] = l;
            f16split(v3, h, l); outHi[cb1 + (size_t)pix1e * 32] = h; outLo[cb1 + (size_t)pix1e * 32] = l;
        }
    }
}

// conv3 (dense 3x3): grid 256 = img*32 + pixtile. 512 thr, fp32 out.
__global__ __launch_bounds__(512, 1)
void conv3_cp(const __half* __restrict__ Wp,
              const float* __restrict__ bias,
              const __half* __restrict__ actHi,
              const __half* __restrict__ actLo,
              float* __restrict__ outF32) {
    extern __shared__ char sm[];
    const int tid  = threadIdx.x;
    const int lane = tid & 31, wid = tid >> 5;
    const int bx   = blockIdx.x;
    const int img  = bx >> 5;
    const int pix0 = (bx & 31) * 128;
    const int h0   = pix0 >> 6;

    constexpr int NCH = 36;
    const uint32_t smem0 = smem_u32(sm);
    const uint32_t dstA0 = smem0 + tid * 16;
    const uint32_t dstB0 = smem0 + 32768 + tid * 16;
    const int bpx = tid & 127;
    const int bch = tid >> 7;

    const __half* aPtr = Wp;
    uint32_t bOff = 0, bOkSz = 0;

    auto setup_tap = [&](int tap) {
        const int dh = tap / 3 - 1, dw = tap % 3 - 1;
        aPtr = Wp + (size_t)tap * 4 * 16384 + tid * 8;
        const int h = h0 + (bpx >> 6) + dh, w = (bpx & 63) + dw;
        const bool ok = ((unsigned)h < 64u) & ((unsigned)w < 64u);
        const int hpix = ok ? (h * 64 + w) : 0;
        bOff = ((uint32_t)(img * 8) * 4096 + hpix) * 32 + bch * 8;
        bOkSz = ok ? 16u : 0u;
    };

    auto issue = [&](int it) {
        const uint32_t sb = (uint32_t)(it & 1) * STG;
        const int kc2 = it & 3;
        if (kc2 == 0) setup_tap(it >> 2);
        const __half* a = aPtr + kc2 * 16384;
#pragma unroll
        for (int i = 0; i < 4; ++i)
            cp16(dstA0 + sb + 8192u * i, a + 4096 * i, 16u);
        const uint32_t base = bOff + (uint32_t)kc2 * 262144u;
        cp16(dstB0 + sb,         actHi + base,           bOkSz);
        cp16(dstB0 + sb + 8192,  actHi + base + 131072,  bOkSz);
        cp16(dstB0 + sb + 16384, actLo + base,           bOkSz);
        cp16(dstB0 + sb + 24576, actLo + base + 131072,  bOkSz);
    };

    float acc[4][4][4];
#pragma unroll
    for (int i = 0; i < 4; i++)
#pragma unroll
        for (int j = 0; j < 4; j++)
#pragma unroll
            for (int k = 0; k < 4; k++) acc[i][j][k] = 0.f;

    const int warp_m = wid >> 2;
    const int warp_n = wid & 3;
    const int lrow = (lane & 7) + ((lane >> 3) & 1) * 8;
    const int lkh  = (lane >> 4);

    issue(0); cp_commit();

    for (int it = 0; it < NCH; ++it) {
        if (it + 1 < NCH) issue(it + 1);
        cp_commit();
        cp_wait1();
        __syncthreads();

        const uint32_t S = smem0 + (it & 1) * STG;
#pragma unroll
        for (int k16 = 0; k16 < 4; ++k16) {
            const int khl = k16 * 2 + lkh;
            const uint32_t kbA = S + khl * 4096;
            const uint32_t kbB = S + 32768 + khl * 2048;
            K16_BODY_F16(kbA, kbB)
        }
        __syncthreads();
    }

    const int l4 = lane >> 2, l2 = lane & 3;
    float* outImg = outF32 + (size_t)img * CT * PIX;
#pragma unroll
    for (int mt = 0; mt < 4; ++mt) {
        const int co0 = warp_m * 64 + mt * 16 + l4;
        const float bi0 = bias[co0], bi1 = bias[co0 + 8];
#pragma unroll
        for (int nt = 0; nt < 4; ++nt) {
            const int p = pix0 + warp_n * 32 + nt * 8 + l2 * 2;
            float v0 = acc[mt][nt][0] + bi0;
            float v1 = acc[mt][nt][1] + bi0;
            float v2 = acc[mt][nt][2] + bi1;
            float v3 = acc[mt][nt][3] + bi1;
            *(float2*)(outImg + (size_t)co0 * PIX + p)       = make_float2(v0, v1);
            *(float2*)(outImg + (size_t)(co0 + 8) * PIX + p) = make_float2(v2, v3);
        }
    }
}

// =====================================================================
// pairwise dots + target norms (unchanged, verified)
// =====================================================================
__global__ __launch_bounds__(256)
void dot_kernel(const float* __restrict__ p, const float* __restrict__ t) {
    const int tid = threadIdx.x;
    const int d0  = blockIdx.x * 2048 + tid;

    float dacc[8][8];
    float tn[8];
#pragma unroll
    for (int i = 0; i < 8; i++) {
        tn[i] = 0.f;
#pragma unroll
        for (int j = 0; j < 8; j++) dacc[i][j] = 0.f;
    }
#pragma unroll 2
    for (int it = 0; it < 8; it++) {
        int d = d0 + it * 256;
        float pv[8], tv[8];
#pragma unroll
        for (int i = 0; i < 8; i++) {
            pv[i] = __ldg(p + (size_t)i * DTOT + d);
            tv[i] = __ldg(t + (size_t)i * DTOT + d);
        }
#pragma unroll
        for (int j = 0; j < 8; j++) tn[j] = fmaf(tv[j], tv[j], tn[j]);
#pragma unroll
        for (int i = 0; i < 8; i++)
#pragma unroll
            for (int j = 0; j < 8; j++)
                dacc[i][j] = fmaf(pv[i], tv[j], dacc[i][j]);
    }
    __shared__ float red[8][72];
    const int lane = tid & 31, warp = tid >> 5;
#pragma unroll
    for (int i = 0; i < 8; i++)
#pragma unroll
        for (int j = 0; j < 8; j++) {
            float v = dacc[i][j];
#pragma unroll
            for (int s = 16; s; s >>= 1) v += __shfl_xor_sync(0xFFFFFFFFu, v, s);
            if (lane == 0) red[warp][i*8+j] = v;
        }
#pragma unroll
    for (int j = 0; j < 8; j++) {
        float v = tn[j];
#pragma unroll
        for (int s = 16; s; s >>= 1) v += __shfl_xor_sync(0xFFFFFFFFu, v, s);
        if (lane == 0) red[warp][64+j] = v;
    }
    __syncthreads();
    if (tid < 72) {
        double s = 0.0;
#pragma unroll
        for (int w = 0; w < 8; w++) s += (double)red[w][tid];
        atomicAdd(&g_acc[tid], s);
    }
}

__global__ void finalize_kernel(float* __restrict__ out) {
    if (threadIdx.x != 0 || blockIdx.x != 0) return;
    double L[8][8];
    for (int i = 0; i < 8; i++)
        for (int j = 0; j < 8; j++)
            L[i][j] = (g_acc[i*8+j] - 0.5 * g_acc[64+j]) / 64.0;
    double ce = 0.0;
    for (int i = 0; i < 8; i++) {
        double m = L[i][0];
        for (int j = 1; j < 8; j++) m = L[i][j] > m ? L[i][j] : m;
        double s = 0.0;
        for (int j = 0; j < 8; j++) s += exp(L[i][j] - m);
        ce += (m + log(s)) - L[i][i];
    }
    ce /= 8.0;
    double loss = ce * (2.0 * 64.0 / 8.0) * 2e-05;
    out[0] = (float)loss;
}

// =====================================================================
extern "C" void kernel_launch(void* const* d_in, const int* in_sizes, int n_in,
                              void* d_out, int out_size) {
    const float* S  = (const float*)d_in[0];
    const float* T  = (const float*)d_in[1];
    const float* Wa = (const float*)d_in[2];
    const float* ba = (const float*)d_in[3];
    const float* W1 = (const float*)d_in[4];
    const float* b1 = (const float*)d_in[5];
    const float* W2 = (const float*)d_in[6];
    const float* b2 = (const float*)d_in[7];
    float* out = (float*)d_out;

    float* tbuf;
    cudaGetSymbolAddress((void**)&tbuf, g_t);
    __nv_bfloat16 *waH, *waL;
    __half *w1h, *w2h, *mHi, *mLo, *g1Hi, *g1Lo;
    cudaGetSymbolAddress((void**)&waH, g_WaHi);
    cudaGetSymbolAddress((void**)&waL, g_WaLo);
    cudaGetSymbolAddress((void**)&w1h, g_W1h);
    cudaGetSymbolAddress((void**)&w2h, g_W2h);
    cudaGetSymbolAddress((void**)&mHi, g_mHi);
    cudaGetSymbolAddress((void**)&mLo, g_mLo);
    cudaGetSymbolAddress((void**)&g1Hi, g_g1Hi);
    cudaGetSymbolAddress((void**)&g1Lo, g_g1Lo);

    cudaFuncSetAttribute(conv1_mma,  cudaFuncAttributeMaxDynamicSharedMemorySize, 65536);
    cudaFuncSetAttribute(conv2_poly, cudaFuncAttributeMaxDynamicSharedMemorySize, 2 * STG);
    cudaFuncSetAttribute(conv3_cp,   cudaFuncAttributeMaxDynamicSharedMemorySize, 2 * STG);

    init_kernel<<<1, 128>>>();
    {
        int total = 256*128 + 36*16384;
        wprep_kernel<<<(total + 255) / 256, 256>>>(Wa, W1, W2);
    }
    conv1_mma <<<dim3(128, 2), 256, 65536>>>(waH, waL, ba, S, mHi, mLo);
    conv2_poly<<<256, 512, 2 * STG>>>(w1h, b1, mHi, mLo, g1Hi, g1Lo);
    conv3_cp  <<<256, 512, 2 * STG>>>(w2h, b2, g1Hi, g1Lo, tbuf);

    dot_kernel<<<DTOT / 2048, 256>>>(T, tbuf);
    finalize_kernel<<<1, 1>>>(out);
}